// round 4
// baseline (speedup 1.0000x reference)
#include <cuda_runtime.h>
#include <cstdint>

// ---------------------------------------------------------------------------
// MCNET binarized CNN (see R0 comments for the algebraic identities used):
//   * sign(maxpool(hardtanh(v))) == sign(max(v))
//   * sign(hardtanh(int n)) == sign(n)
//   * L2..L4 activations are ternary {-1,0,+1} stored as int8 sign maps
// R3 changes: vectorized weight LDS (LDS.128/LDS.64), warp-uniform weight
// addresses in l3 (og from bits[6:7]), 4 pixels/thread in l2.
// ---------------------------------------------------------------------------

// Intermediate sign maps, NHWC int8, packed in vector types.
static __device__ uint2 g_s1[32u * 256 * 256];       // [b,y,x, 8ch]  16.8 MB
static __device__ int4  g_s2[32u * 254 * 254];       // [b,y,x,16ch]  33.0 MB
static __device__ int4  g_s3[32u * 252 * 252 * 2];   // [b,y,x,32ch]  65.0 MB

// Sign weights (prepared on device each launch).
static __device__ float g_w1f[216];    // [o=8][c=3][ky][kx] as float +-1/0
static __device__ int   g_w2p[288];    // [o=16][9 pos][2 packs of 4ch]  (int2-aligned)
static __device__ int   g_w3p[1152];   // [o=32][9 pos][4 packs of 4ch]  (int4-aligned)
static __device__ int   g_w4p[144];    // [o=2 ][9 pos][8 packs of 4ch]  (int4-aligned)

__device__ __forceinline__ int sgnf(float v) { return (v > 0.f) - (v < 0.f); }
__device__ __forceinline__ int sgni(int v)   { return (v > 0) - (v < 0); }
__device__ __forceinline__ int pack4(int a, int b, int c, int d) {
    return (a & 0xFF) | ((b & 0xFF) << 8) | ((c & 0xFF) << 16) | ((d & 0xFF) << 24);
}

// ---------------------------------------------------------------------------
// Weight prep: binarize + pack. Tiny; one block.
// ---------------------------------------------------------------------------
__global__ void prep_kernel(const float* __restrict__ w1, const float* __restrict__ w2,
                            const float* __restrict__ w3, const float* __restrict__ w4) {
    int t = threadIdx.x;
    for (int i = t; i < 216; i += blockDim.x) g_w1f[i] = (float)sgnf(w1[i]);
    for (int i = t; i < 288; i += blockDim.x) {
        int h = i & 1, pos = (i >> 1) % 9, o = i / 18;
        int ky = pos / 3, kx = pos % 3;
        int s[4];
        #pragma unroll
        for (int j = 0; j < 4; j++)
            s[j] = sgnf(w2[((o * 8 + (4 * h + j)) * 3 + ky) * 3 + kx]);
        g_w2p[i] = pack4(s[0], s[1], s[2], s[3]);
    }
    for (int i = t; i < 1152; i += blockDim.x) {
        int q = i & 3, pos = (i >> 2) % 9, o = i / 36;
        int ky = pos / 3, kx = pos % 3;
        int s[4];
        #pragma unroll
        for (int j = 0; j < 4; j++)
            s[j] = sgnf(w3[((o * 16 + (4 * q + j)) * 3 + ky) * 3 + kx]);
        g_w3p[i] = pack4(s[0], s[1], s[2], s[3]);
    }
    for (int i = t; i < 144; i += blockDim.x) {
        int q = i & 7, pos = (i >> 3) % 9, o = i / 72;
        int ky = pos / 3, kx = pos % 3;
        int s[4];
        #pragma unroll
        for (int j = 0; j < 4; j++)
            s[j] = sgnf(w4[((o * 32 + (4 * q + j)) * 3 + ky) * 3 + kx]);
        g_w4p[i] = pack4(s[0], s[1], s[2], s[3]);
    }
}

// ---------------------------------------------------------------------------
// Layer 1: fp conv (3->8), pad value 1.0, fused hardtanh+maxpool+sign.
// One thread = one pooled pixel (b,py,px), all 8 out channels.
// ---------------------------------------------------------------------------
__global__ __launch_bounds__(256)
void l1_kernel(const float* __restrict__ x) {
    __shared__ float sw[216];
    for (int i = threadIdx.x; i < 216; i += blockDim.x) sw[i] = g_w1f[i];
    __syncthreads();

    int t = blockIdx.x * blockDim.x + threadIdx.x;   // 32*256*256 threads exact
    int px = t & 255;
    int py = (t >> 8) & 255;
    int b  = t >> 16;

    float acc[4][8];
    #pragma unroll
    for (int p = 0; p < 4; p++)
        #pragma unroll
        for (int o = 0; o < 8; o++) acc[p][o] = 0.f;

    int gy0 = 2 * py - 1;
    int gx0 = 2 * px - 1;

    #pragma unroll
    for (int c = 0; c < 3; c++) {
        float p[4][4];
        const float* xc = x + ((size_t)b * 3 + c) * 512 * 512;
        #pragma unroll
        for (int r = 0; r < 4; r++) {
            int gy = gy0 + r;
            bool rok = (unsigned)gy < 512u;
            #pragma unroll
            for (int cc = 0; cc < 4; cc++) {
                int gx = gx0 + cc;
                bool ok = rok && ((unsigned)gx < 512u);
                p[r][cc] = ok ? __ldg(xc + gy * 512 + gx) : 1.0f;
            }
        }
        #pragma unroll
        for (int ky = 0; ky < 3; ky++)
            #pragma unroll
            for (int kx = 0; kx < 3; kx++)
                #pragma unroll
                for (int o = 0; o < 8; o++) {
                    float w = sw[((o * 3 + c) * 3 + ky) * 3 + kx];
                    #pragma unroll
                    for (int dy = 0; dy < 2; dy++)
                        #pragma unroll
                        for (int dx = 0; dx < 2; dx++)
                            acc[dy * 2 + dx][o] = fmaf(p[ky + dy][kx + dx], w,
                                                       acc[dy * 2 + dx][o]);
                }
    }

    int s[8];
    #pragma unroll
    for (int o = 0; o < 8; o++) {
        float m = fmaxf(fmaxf(acc[0][o], acc[1][o]), fmaxf(acc[2][o], acc[3][o]));
        s[o] = sgnf(m);
    }
    uint2 out;
    out.x = (unsigned)pack4(s[0], s[1], s[2], s[3]);
    out.y = (unsigned)pack4(s[4], s[5], s[6], s[7]);
    g_s1[((size_t)b * 256 + py) * 256 + px] = out;
}

// ---------------------------------------------------------------------------
// Layer 2: ternary conv (8->16). One thread = 4 x-adjacent pixels, all 16 oc.
// 64 xg slots per row (slot 63 duplicates x0=250; identical stores, benign).
// Weight loads are int2 (LDS.64), uniform per warp.
// ---------------------------------------------------------------------------
__global__ __launch_bounds__(256)
void l2_kernel() {
    __shared__ int sw[288];
    for (int i = threadIdx.x; i < 288; i += blockDim.x) sw[i] = g_w2p[i];
    __syncthreads();
    const int2* sw2 = (const int2*)sw;               // [o*9 + pos]

    int t = blockIdx.x * blockDim.x + threadIdx.x;   // 32*254*64 exact
    int xg = t & 63;
    int r1 = t >> 6;
    int y  = r1 % 254;
    int b  = r1 / 254;
    int x0 = xg * 4; if (x0 > 250) x0 = 250;

    int acc[4][16];
    #pragma unroll
    for (int p = 0; p < 4; p++)
        #pragma unroll
        for (int o = 0; o < 16; o++) acc[p][o] = 0;

    #pragma unroll
    for (int ky = 0; ky < 3; ky++) {
        uint2 d[6];                                  // cols x0..x0+5, 8ch each
        size_t base = ((size_t)b * 256 + (y + ky)) * 256 + x0;
        #pragma unroll
        for (int cc = 0; cc < 6; cc++) d[cc] = g_s1[base + cc];

        #pragma unroll
        for (int o = 0; o < 16; o++)
            #pragma unroll
            for (int kx = 0; kx < 3; kx++) {
                int2 w = sw2[o * 9 + ky * 3 + kx];
                #pragma unroll
                for (int p = 0; p < 4; p++) {
                    acc[p][o] = __dp4a((int)d[kx + p].x, w.x, acc[p][o]);
                    acc[p][o] = __dp4a((int)d[kx + p].y, w.y, acc[p][o]);
                }
            }
    }

    #pragma unroll
    for (int p = 0; p < 4; p++) {
        int4 out;
        out.x = pack4(sgni(acc[p][0]),  sgni(acc[p][1]),  sgni(acc[p][2]),  sgni(acc[p][3]));
        out.y = pack4(sgni(acc[p][4]),  sgni(acc[p][5]),  sgni(acc[p][6]),  sgni(acc[p][7]));
        out.z = pack4(sgni(acc[p][8]),  sgni(acc[p][9]),  sgni(acc[p][10]), sgni(acc[p][11]));
        out.w = pack4(sgni(acc[p][12]), sgni(acc[p][13]), sgni(acc[p][14]), sgni(acc[p][15]));
        g_s2[((size_t)b * 254 + y) * 254 + (x0 + p)] = out;
    }
}

// ---------------------------------------------------------------------------
// Layer 3: ternary conv (16->32). One thread = 4 x-adjacent pixels, 8-oc group.
// og in bits[6:7] of linear id -> uniform per warp -> broadcast LDS.128.
// 64 xg slots (slot 63 duplicates x0=248; identical stores, benign).
// ---------------------------------------------------------------------------
__global__ __launch_bounds__(256)
void l3_kernel() {
    __shared__ int sw[1152];
    for (int i = threadIdx.x; i < 1152; i += blockDim.x) sw[i] = g_w3p[i];
    __syncthreads();
    const int4* sw4 = (const int4*)sw;               // [(og*8+o)*9 + pos]

    int t = blockIdx.x * blockDim.x + threadIdx.x;   // 32*252*4*64 exact
    int xg = t & 63;
    int og = (t >> 6) & 3;
    int r1 = t >> 8;
    int y  = r1 % 252;
    int b  = r1 / 252;
    int x0 = xg * 4; if (x0 > 248) x0 = 248;

    int acc[4][8];
    #pragma unroll
    for (int p = 0; p < 4; p++)
        #pragma unroll
        for (int o = 0; o < 8; o++) acc[p][o] = 0;

    #pragma unroll
    for (int ky = 0; ky < 3; ky++) {
        int r[24];                                   // cols x0..x0+5, 16ch each
        size_t base = ((size_t)b * 254 + (y + ky)) * 254 + x0;
        #pragma unroll
        for (int cc = 0; cc < 6; cc++) {
            int4 v = g_s2[base + cc];
            r[cc * 4 + 0] = v.x; r[cc * 4 + 1] = v.y;
            r[cc * 4 + 2] = v.z; r[cc * 4 + 3] = v.w;
        }
        #pragma unroll
        for (int kx = 0; kx < 3; kx++)
            #pragma unroll
            for (int o = 0; o < 8; o++) {
                int4 w = sw4[(og * 8 + o) * 9 + ky * 3 + kx];
                #pragma unroll
                for (int p = 0; p < 4; p++) {
                    acc[p][o] = __dp4a(r[(kx + p) * 4 + 0], w.x, acc[p][o]);
                    acc[p][o] = __dp4a(r[(kx + p) * 4 + 1], w.y, acc[p][o]);
                    acc[p][o] = __dp4a(r[(kx + p) * 4 + 2], w.z, acc[p][o]);
                    acc[p][o] = __dp4a(r[(kx + p) * 4 + 3], w.w, acc[p][o]);
                }
            }
    }

    uint2* s3 = (uint2*)g_s3;                        // pixel = 4 uint2 (32 ch)
    #pragma unroll
    for (int p = 0; p < 4; p++) {
        uint2 out;
        out.x = (unsigned)pack4(sgni(acc[p][0]), sgni(acc[p][1]),
                                sgni(acc[p][2]), sgni(acc[p][3]));
        out.y = (unsigned)pack4(sgni(acc[p][4]), sgni(acc[p][5]),
                                sgni(acc[p][6]), sgni(acc[p][7]));
        s3[(((size_t)b * 252 + y) * 252 + (x0 + p)) * 4 + og] = out;
    }
}

// ---------------------------------------------------------------------------
// Layer 4: ternary conv (32->2) + hardtanh -> fp32 out (NCHW flattened).
// One thread = 2 x-adjacent pixels, both oc. Weight loads are 2x LDS.128.
// ---------------------------------------------------------------------------
__global__ __launch_bounds__(256)
void l4_kernel(float* __restrict__ out) {
    __shared__ int sw[144];
    for (int i = threadIdx.x; i < 144; i += blockDim.x) sw[i] = g_w4p[i];
    __syncthreads();
    const int4* sw4 = (const int4*)sw;               // [(o*9+pos)*2 + half]

    int t = blockIdx.x * blockDim.x + threadIdx.x;
    const int TOT = 32 * 250 * 125;
    if (t >= TOT) return;
    int xg = t % 125;
    int y  = (t / 125) % 250;
    int b  = t / (125 * 250);
    int x0 = xg * 2;

    int acc[2][2];
    acc[0][0] = acc[0][1] = acc[1][0] = acc[1][1] = 0;

    #pragma unroll
    for (int ky = 0; ky < 3; ky++) {
        int r[32];                                   // cols x0..x0+3, 32ch each
        size_t base = (((size_t)b * 252 + (y + ky)) * 252 + x0) * 2;
        #pragma unroll
        for (int cc = 0; cc < 4; cc++) {
            int4 v0 = g_s3[base + cc * 2 + 0];
            int4 v1 = g_s3[base + cc * 2 + 1];
            r[cc * 8 + 0] = v0.x; r[cc * 8 + 1] = v0.y;
            r[cc * 8 + 2] = v0.z; r[cc * 8 + 3] = v0.w;
            r[cc * 8 + 4] = v1.x; r[cc * 8 + 5] = v1.y;
            r[cc * 8 + 6] = v1.z; r[cc * 8 + 7] = v1.w;
        }
        #pragma unroll
        for (int kx = 0; kx < 3; kx++)
            #pragma unroll
            for (int o = 0; o < 2; o++) {
                int4 wa = sw4[(o * 9 + ky * 3 + kx) * 2 + 0];
                int4 wb = sw4[(o * 9 + ky * 3 + kx) * 2 + 1];
                #pragma unroll
                for (int p = 0; p < 2; p++) {
                    const int* rp = &r[(kx + p) * 8];
                    acc[p][o] = __dp4a(rp[0], wa.x, acc[p][o]);
                    acc[p][o] = __dp4a(rp[1], wa.y, acc[p][o]);
                    acc[p][o] = __dp4a(rp[2], wa.z, acc[p][o]);
                    acc[p][o] = __dp4a(rp[3], wa.w, acc[p][o]);
                    acc[p][o] = __dp4a(rp[4], wb.x, acc[p][o]);
                    acc[p][o] = __dp4a(rp[5], wb.y, acc[p][o]);
                    acc[p][o] = __dp4a(rp[6], wb.z, acc[p][o]);
                    acc[p][o] = __dp4a(rp[7], wb.w, acc[p][o]);
                }
            }
    }

    #pragma unroll
    for (int p = 0; p < 2; p++)
        #pragma unroll
        for (int o = 0; o < 2; o++) {
            float v = fminf(fmaxf((float)acc[p][o], -1.f), 1.f);
            out[(size_t)b * 125000 + (size_t)o * 62500 + (size_t)y * 250 + (x0 + p)] = v;
        }
}

// ---------------------------------------------------------------------------
extern "C" void kernel_launch(void* const* d_in, const int* in_sizes, int n_in,
                              void* d_out, int out_size) {
    const float* x  = (const float*)d_in[0];
    const float* w1 = (const float*)d_in[1];
    const float* w2 = (const float*)d_in[2];
    const float* w3 = (const float*)d_in[3];
    const float* w4 = (const float*)d_in[4];
    float* out = (float*)d_out;

    prep_kernel<<<1, 256>>>(w1, w2, w3, w4);
    l1_kernel<<<8192, 256>>>(x);                    // 32*256*256 threads
    l2_kernel<<<2032, 256>>>();                     // 32*254*64 threads
    l3_kernel<<<8064, 256>>>();                     // 32*252*4*64 threads
    l4_kernel<<<(32 * 250 * 125 + 255) / 256, 256>>>(out);
}

// round 5
// speedup vs baseline: 1.1400x; 1.1400x over previous
#include <cuda_runtime.h>
#include <cstdint>

// ---------------------------------------------------------------------------
// MCNET binarized CNN (algebraic identities, see R0):
//   * sign(maxpool(hardtanh(v))) == sign(max(v))
//   * sign(hardtanh(int n)) == sign(n)
//   * L2..L4 activations are ternary {-1,0,+1} int8 sign maps
// R5 changes: y-amortized threads (lane = x pixel -> fully coalesced LDG/STG),
// l3 split into two 4-oc passes (fewer regs, higher occupancy), g_s3 stored
// plane-major so l3 stores / l4 loads are 4B-per-lane coalesced.
// ---------------------------------------------------------------------------

static __device__ uint2    g_s1[32u * 256 * 256];          // [b,y,x, 8ch]  16.8 MB
static __device__ int4     g_s2[32u * 254 * 254];          // [b,y,x,16ch]  33.0 MB
static __device__ unsigned g_s3u[8][32u * 252 * 252];      // [chgroup][b,y,x] 65 MB

static __device__ float g_w1f[216];    // [o=8][c=3][ky][kx] as float +-1/0
static __device__ int   g_w2p[288];    // [o=16][9 pos][2 packs of 4ch]
static __device__ int   g_w3p[1152];   // [o=32][9 pos][4 packs of 4ch]
static __device__ int   g_w4p[144];    // [o=2 ][9 pos][8 packs of 4ch]

__device__ __forceinline__ int sgnf(float v) { return (v > 0.f) - (v < 0.f); }
__device__ __forceinline__ int sgni(int v)   { return (v > 0) - (v < 0); }
__device__ __forceinline__ int pack4(int a, int b, int c, int d) {
    return (a & 0xFF) | ((b & 0xFF) << 8) | ((c & 0xFF) << 16) | ((d & 0xFF) << 24);
}

// ---------------------------------------------------------------------------
__global__ void prep_kernel(const float* __restrict__ w1, const float* __restrict__ w2,
                            const float* __restrict__ w3, const float* __restrict__ w4) {
    int t = threadIdx.x;
    for (int i = t; i < 216; i += blockDim.x) g_w1f[i] = (float)sgnf(w1[i]);
    for (int i = t; i < 288; i += blockDim.x) {
        int h = i & 1, pos = (i >> 1) % 9, o = i / 18;
        int ky = pos / 3, kx = pos % 3;
        int s[4];
        #pragma unroll
        for (int j = 0; j < 4; j++)
            s[j] = sgnf(w2[((o * 8 + (4 * h + j)) * 3 + ky) * 3 + kx]);
        g_w2p[i] = pack4(s[0], s[1], s[2], s[3]);
    }
    for (int i = t; i < 1152; i += blockDim.x) {
        int q = i & 3, pos = (i >> 2) % 9, o = i / 36;
        int ky = pos / 3, kx = pos % 3;
        int s[4];
        #pragma unroll
        for (int j = 0; j < 4; j++)
            s[j] = sgnf(w3[((o * 16 + (4 * q + j)) * 3 + ky) * 3 + kx]);
        g_w3p[i] = pack4(s[0], s[1], s[2], s[3]);
    }
    for (int i = t; i < 144; i += blockDim.x) {
        int q = i & 7, pos = (i >> 3) % 9, o = i / 72;
        int ky = pos / 3, kx = pos % 3;
        int s[4];
        #pragma unroll
        for (int j = 0; j < 4; j++)
            s[j] = sgnf(w4[((o * 32 + (4 * q + j)) * 3 + ky) * 3 + kx]);
        g_w4p[i] = pack4(s[0], s[1], s[2], s[3]);
    }
}

// ---------------------------------------------------------------------------
// Layer 1: fp conv (3->8), pad 1.0, fused hardtanh+maxpool+sign. Unchanged.
// ---------------------------------------------------------------------------
__global__ __launch_bounds__(256)
void l1_kernel(const float* __restrict__ x) {
    __shared__ float sw[216];
    for (int i = threadIdx.x; i < 216; i += blockDim.x) sw[i] = g_w1f[i];
    __syncthreads();

    int t = blockIdx.x * blockDim.x + threadIdx.x;   // 32*256*256 threads exact
    int px = t & 255;
    int py = (t >> 8) & 255;
    int b  = t >> 16;

    float acc[4][8];
    #pragma unroll
    for (int p = 0; p < 4; p++)
        #pragma unroll
        for (int o = 0; o < 8; o++) acc[p][o] = 0.f;

    int gy0 = 2 * py - 1;
    int gx0 = 2 * px - 1;

    #pragma unroll
    for (int c = 0; c < 3; c++) {
        float p[4][4];
        const float* xc = x + ((size_t)b * 3 + c) * 512 * 512;
        #pragma unroll
        for (int r = 0; r < 4; r++) {
            int gy = gy0 + r;
            bool rok = (unsigned)gy < 512u;
            #pragma unroll
            for (int cc = 0; cc < 4; cc++) {
                int gx = gx0 + cc;
                bool ok = rok && ((unsigned)gx < 512u);
                p[r][cc] = ok ? __ldg(xc + gy * 512 + gx) : 1.0f;
            }
        }
        #pragma unroll
        for (int ky = 0; ky < 3; ky++)
            #pragma unroll
            for (int kx = 0; kx < 3; kx++)
                #pragma unroll
                for (int o = 0; o < 8; o++) {
                    float w = sw[((o * 3 + c) * 3 + ky) * 3 + kx];
                    #pragma unroll
                    for (int dy = 0; dy < 2; dy++)
                        #pragma unroll
                        for (int dx = 0; dx < 2; dx++)
                            acc[dy * 2 + dx][o] = fmaf(p[ky + dy][kx + dx], w,
                                                       acc[dy * 2 + dx][o]);
                }
    }

    int s[8];
    #pragma unroll
    for (int o = 0; o < 8; o++) {
        float m = fmaxf(fmaxf(acc[0][o], acc[1][o]), fmaxf(acc[2][o], acc[3][o]));
        s[o] = sgnf(m);
    }
    uint2 out;
    out.x = (unsigned)pack4(s[0], s[1], s[2], s[3]);
    out.y = (unsigned)pack4(s[4], s[5], s[6], s[7]);
    g_s1[((size_t)b * 256 + py) * 256 + px] = out;
}

// ---------------------------------------------------------------------------
// Layer 2: ternary conv (8->16). Block = (b, 2-row group). Thread = one x
// (lane-consecutive -> coalesced uint2 loads / int4 stores), 2 y rows, 16 oc.
// ---------------------------------------------------------------------------
__global__ __launch_bounds__(256)
void l2_kernel() {
    __shared__ int sw[288];
    for (int i = threadIdx.x; i < 288; i += blockDim.x) sw[i] = g_w2p[i];
    __syncthreads();
    const int2* sw2 = (const int2*)sw;               // [o*9 + pos]

    int b  = blockIdx.x / 127;
    int y0 = (blockIdx.x % 127) * 2;
    int x  = threadIdx.x;
    if (x >= 254) return;

    int acc[2][16];
    #pragma unroll
    for (int p = 0; p < 2; p++)
        #pragma unroll
        for (int o = 0; o < 16; o++) acc[p][o] = 0;

    #pragma unroll
    for (int cc = 0; cc < 3; cc++) {
        uint2 d[4];                                  // rows y0..y0+3 at col x+cc
        #pragma unroll
        for (int r = 0; r < 4; r++)
            d[r] = g_s1[((size_t)b * 256 + (y0 + r)) * 256 + (x + cc)];
        #pragma unroll
        for (int ky = 0; ky < 3; ky++)
            #pragma unroll
            for (int o = 0; o < 16; o++) {
                int2 w = sw2[o * 9 + ky * 3 + cc];
                #pragma unroll
                for (int p = 0; p < 2; p++) {
                    acc[p][o] = __dp4a((int)d[ky + p].x, w.x, acc[p][o]);
                    acc[p][o] = __dp4a((int)d[ky + p].y, w.y, acc[p][o]);
                }
            }
    }

    #pragma unroll
    for (int p = 0; p < 2; p++) {
        int4 out;
        out.x = pack4(sgni(acc[p][0]),  sgni(acc[p][1]),  sgni(acc[p][2]),  sgni(acc[p][3]));
        out.y = pack4(sgni(acc[p][4]),  sgni(acc[p][5]),  sgni(acc[p][6]),  sgni(acc[p][7]));
        out.z = pack4(sgni(acc[p][8]),  sgni(acc[p][9]),  sgni(acc[p][10]), sgni(acc[p][11]));
        out.w = pack4(sgni(acc[p][12]), sgni(acc[p][13]), sgni(acc[p][14]), sgni(acc[p][15]));
        g_s2[((size_t)b * 254 + (y0 + p)) * 254 + x] = out;
    }
}

// ---------------------------------------------------------------------------
// Layer 3: ternary conv (16->32). Block = (b, 4-row group, og of 8 oc).
// Thread = one x (coalesced int4 loads), 4 y rows. Two 4-oc passes keep
// acc at 16 regs -> higher occupancy. Stores 4B/lane into plane-major g_s3u.
// ---------------------------------------------------------------------------
__global__ __launch_bounds__(256)
void l3_kernel() {
    __shared__ int sw[288];                          // weights for this og only
    int blk = blockIdx.x;
    int og  = blk & 3;
    int yg  = (blk >> 2) % 63;
    int b   = blk / 252;                             // 252 = 63*4 blocks per b
    for (int i = threadIdx.x; i < 288; i += blockDim.x) sw[i] = g_w3p[og * 288 + i];
    __syncthreads();
    const int4* sw4 = (const int4*)sw;               // [o*9 + pos], o in 0..7

    int x = threadIdx.x;
    if (x >= 252) return;
    int y0 = yg * 4;

    #pragma unroll
    for (int oh = 0; oh < 2; oh++) {
        int acc[4][4];
        #pragma unroll
        for (int p = 0; p < 4; p++)
            #pragma unroll
            for (int o = 0; o < 4; o++) acc[p][o] = 0;

        #pragma unroll
        for (int cc = 0; cc < 3; cc++) {
            int4 d[6];                               // rows y0..y0+5 at col x+cc
            #pragma unroll
            for (int r = 0; r < 6; r++)
                d[r] = g_s2[((size_t)b * 254 + (y0 + r)) * 254 + (x + cc)];
            #pragma unroll
            for (int ky = 0; ky < 3; ky++)
                #pragma unroll
                for (int o = 0; o < 4; o++) {
                    int4 w = sw4[(oh * 4 + o) * 9 + ky * 3 + cc];
                    #pragma unroll
                    for (int p = 0; p < 4; p++) {
                        acc[p][o] = __dp4a(d[ky + p].x, w.x, acc[p][o]);
                        acc[p][o] = __dp4a(d[ky + p].y, w.y, acc[p][o]);
                        acc[p][o] = __dp4a(d[ky + p].z, w.z, acc[p][o]);
                        acc[p][o] = __dp4a(d[ky + p].w, w.w, acc[p][o]);
                    }
                }
        }

        unsigned* plane = g_s3u[og * 2 + oh];        // 4 channels og*8+oh*4 ..
        #pragma unroll
        for (int p = 0; p < 4; p++) {
            unsigned v = (unsigned)pack4(sgni(acc[p][0]), sgni(acc[p][1]),
                                         sgni(acc[p][2]), sgni(acc[p][3]));
            plane[((size_t)b * 252 + (y0 + p)) * 252 + x] = v;
        }
    }
}

// ---------------------------------------------------------------------------
// Layer 4: ternary conv (32->2) + hardtanh -> fp32 out. Block = (b, 2-row
// group). Thread = one x (coalesced), 2 y rows, both oc.
// ---------------------------------------------------------------------------
__global__ __launch_bounds__(256)
void l4_kernel(float* __restrict__ out) {
    __shared__ int sw[144];
    for (int i = threadIdx.x; i < 144; i += blockDim.x) sw[i] = g_w4p[i];
    __syncthreads();
    const int4* sw4 = (const int4*)sw;               // [(o*9+pos)*2 + half]

    int b  = blockIdx.x / 125;
    int y0 = (blockIdx.x % 125) * 2;
    int x  = threadIdx.x;
    if (x >= 250) return;

    int acc[2][2];
    acc[0][0] = acc[0][1] = acc[1][0] = acc[1][1] = 0;

    #pragma unroll
    for (int cc = 0; cc < 3; cc++) {
        unsigned d[4][8];                            // rows y0..y0+3, 8 planes
        #pragma unroll
        for (int r = 0; r < 4; r++) {
            size_t pix = ((size_t)b * 252 + (y0 + r)) * 252 + (x + cc);
            #pragma unroll
            for (int q = 0; q < 8; q++) d[r][q] = g_s3u[q][pix];
        }
        #pragma unroll
        for (int ky = 0; ky < 3; ky++)
            #pragma unroll
            for (int o = 0; o < 2; o++) {
                int4 wa = sw4[(o * 9 + ky * 3 + cc) * 2 + 0];
                int4 wb = sw4[(o * 9 + ky * 3 + cc) * 2 + 1];
                #pragma unroll
                for (int p = 0; p < 2; p++) {
                    const unsigned* dr = d[ky + p];
                    acc[p][o] = __dp4a((int)dr[0], wa.x, acc[p][o]);
                    acc[p][o] = __dp4a((int)dr[1], wa.y, acc[p][o]);
                    acc[p][o] = __dp4a((int)dr[2], wa.z, acc[p][o]);
                    acc[p][o] = __dp4a((int)dr[3], wa.w, acc[p][o]);
                    acc[p][o] = __dp4a((int)dr[4], wb.x, acc[p][o]);
                    acc[p][o] = __dp4a((int)dr[5], wb.y, acc[p][o]);
                    acc[p][o] = __dp4a((int)dr[6], wb.z, acc[p][o]);
                    acc[p][o] = __dp4a((int)dr[7], wb.w, acc[p][o]);
                }
            }
    }

    #pragma unroll
    for (int p = 0; p < 2; p++)
        #pragma unroll
        for (int o = 0; o < 2; o++) {
            float v = fminf(fmaxf((float)acc[p][o], -1.f), 1.f);
            out[(size_t)b * 125000 + (size_t)o * 62500 + (size_t)(y0 + p) * 250 + x] = v;
        }
}

// ---------------------------------------------------------------------------
extern "C" void kernel_launch(void* const* d_in, const int* in_sizes, int n_in,
                              void* d_out, int out_size) {
    const float* x  = (const float*)d_in[0];
    const float* w1 = (const float*)d_in[1];
    const float* w2 = (const float*)d_in[2];
    const float* w3 = (const float*)d_in[3];
    const float* w4 = (const float*)d_in[4];
    float* out = (float*)d_out;

    prep_kernel<<<1, 256>>>(w1, w2, w3, w4);
    l1_kernel<<<8192, 256>>>(x);                    // 32*256*256 threads
    l2_kernel<<<32 * 127, 256>>>();                 // block = (b, 2 rows)
    l3_kernel<<<32 * 63 * 4, 256>>>();              // block = (b, 4 rows, og)
    l4_kernel<<<32 * 125, 256>>>(out);              // block = (b, 2 rows)
}